// round 13
// baseline (speedup 1.0000x reference)
#include <cuda_runtime.h>
#include <cuda_fp16.h>
#include <stdint.h>

#define DIMS   128
#define KCODES 512
#define NB     32
#define HW     4096
#define NROWS  131072
#define ZSTRB  524288

#define OFF_Q    ((size_t)0)
#define OFF_LOSS ((size_t)16777216)
#define OFF_IDX  ((size_t)16777217)
#define OFF_EMB  ((size_t)16908289)
#define OFF_CS   ((size_t)16973825)
#define OFF_EA   ((size_t)16974337)

#define TAU 0.12f
#define FIXB 16

// ---------------- device scratch ----------------
__device__ __half g_Bh[KCODES * DIMS];       // emb hi split, [code][d]
__device__ unsigned long long g_minkey[NROWS];
__device__ float g_embed_sum[DIMS * KCODES];
__device__ int   g_counts[KCODES];
__device__ float g_loss;
__device__ float g_enorm[KCODES];
__device__ float g_cs[KCODES];
__device__ int   g_idx[NROWS];
__device__ int   g_nfix;
__device__ int   g_fixlist[NROWS];

// ---------------- helpers ----------------
__device__ __forceinline__ unsigned fenc(float f) {
    unsigned u = __float_as_uint(f);
    return (u & 0x80000000u) ? ~u : (u | 0x80000000u);
}
__device__ __forceinline__ float fdec(unsigned e) {
    return (e & 0x80000000u) ? __uint_as_float(e ^ 0x80000000u)
                             : __uint_as_float(~e);
}
__device__ __forceinline__ void mma16816(float* d, const uint32_t* a, const uint32_t* b) {
    asm volatile(
        "mma.sync.aligned.m16n8k16.row.col.f32.f16.f16.f32 "
        "{%0,%1,%2,%3}, {%4,%5,%6,%7}, {%8,%9}, {%0,%1,%2,%3};"
        : "+f"(d[0]), "+f"(d[1]), "+f"(d[2]), "+f"(d[3])
        : "r"(a[0]), "r"(a[1]), "r"(a[2]), "r"(a[3]), "r"(b[0]), "r"(b[1]));
}
__device__ __forceinline__ void ldsm4(uint32_t* r, uint32_t addr) {
    asm volatile(
        "ldmatrix.sync.aligned.m8n8.x4.shared.b16 {%0,%1,%2,%3}, [%4];"
        : "=r"(r[0]), "=r"(r[1]), "=r"(r[2]), "=r"(r[3]) : "r"(addr));
}

// ---------------- K: zero scratch ----------------
__global__ void k_zero() {
    int i = blockIdx.x * 256 + threadIdx.x;            // 256 x 256
    g_embed_sum[i] = 0.f;
    if (i < KCODES) g_counts[i] = 0;
    if (i == 0) { g_loss = 0.f; g_nfix = 0; }
}

// ---------------- K: embedding hi split + norms ----------------
__global__ void k_bsplit(const float* __restrict__ emb) {
    int d = blockIdx.x;                                // 128
    int k = threadIdx.x;                               // 512
    g_Bh[(size_t)k * DIMS + d] = __float2half_rn(emb[d * KCODES + k]);
}

__global__ void k_enorm(const float* __restrict__ emb) {
    int k = blockIdx.x * 256 + threadIdx.x;            // 2 x 256
    float s = 0.f;
    #pragma unroll 8
    for (int d = 0; d < DIMS; d++) {
        float e = emb[d * KCODES + k];
        s = fmaf(e, e, s);
    }
    g_enorm[k] = s;
}

// ---------------- K: persistent fused GEMM + argmin + decode + gather ------
#define APITCH 272
#define SB_OFF 0                           // 512 x 272 = 139264
#define SA0    139264                      // 2 x 34816 A buffers
#define EN_OFF 208896                      // 512 floats
#define SBEST  210944                      // 128 u64
#define SSEC   211968                      // 128 u64
#define XRED2  212992                      // 2 x 128 floats
#define SIDX   214016                      // 128 ints
#define LRED   214528                      // 128 floats
#define SM_GEMM 215040

__global__ __launch_bounds__(512, 1)
void k_gemm(const float* __restrict__ z, const float* __restrict__ emb,
            float* __restrict__ out) {
    extern __shared__ char smc[];
    const int tid = threadIdx.x;
    const int wid = tid >> 5, lane = tid & 31;
    const int t4 = lane & 3;
    const int slot = blockIdx.x;                      // 0..147
    const int njobs = (1023 - slot) / 148 + 1;        // 6 or 7 tiles
    const int mr = (wid & 3) * 32;                    // warp row base
    const int nc = (wid >> 2) * 64;                   // warp col base

    float* en_s = (float*)(smc + EN_OFF);
    unsigned long long* sbest = (unsigned long long*)(smc + SBEST);
    unsigned long long* ssec  = (unsigned long long*)(smc + SSEC);
    float* xred = (float*)(smc + XRED2);              // [2][128]
    int*   s_idx = (int*)(smc + SIDX);
    float* lred = (float*)(smc + LRED);

    // B: all 512 codes resident, loaded ONCE
    for (int i = tid; i < 8192; i += 512) {
        int row = i >> 4, c = i & 15;
        *(uint4*)(smc + SB_OFF + row * APITCH + c * 16) =
            *(const uint4*)(g_Bh + (size_t)row * DIMS + c * 8);
    }
    en_s[tid] = g_enorm[tid];
    if (tid < 128) xred[tid] = 0.f;                   // buffer 0
    __syncthreads();

    const int r = tid & 127, j = tid >> 7;            // j = 0..3
    auto prefetch = [&](int mt, int buf) {
        const float* zp = z + (size_t)(mt >> 5) * ZSTRB + ((mt & 31) << 7) + r;
        float xn = 0.f;
        #pragma unroll
        for (int it = 0; it < 16; it++) {
            const int dp = j + 4 * it;                // dim pair 0..63
            float a = zp[(size_t)(2 * dp) * HW];
            float b = zp[(size_t)(2 * dp + 1) * HW];
            *(__half2*)(smc + SA0 + buf * 34816 + r * APITCH + dp * 4) =
                __floats2half2_rn(a, b);
            xn = fmaf(a, a, fmaf(b, b, xn));
        }
        atomicAdd(&xred[buf * 128 + r], xn);
    };
    prefetch(slot, 0);                                // fill A[0] for tile 0

    const uint32_t sa = (uint32_t)__cvta_generic_to_shared(smc + SA0);
    const uint32_t sb = (uint32_t)__cvta_generic_to_shared(smc + SB_OFF);
    uint32_t a_addr[2], b_addr[4];
    #pragma unroll
    for (int mt = 0; mt < 2; mt++)
        a_addr[mt] = sa + (mr + mt * 16 + (lane & 15)) * APITCH + ((lane >> 4) << 4);
    #pragma unroll
    for (int p = 0; p < 4; p++)
        b_addr[p] = sb + (nc + p * 16 + ((lane >> 4) << 3) + (lane & 7)) * APITCH
                       + (((lane >> 3) & 1) << 4);

    for (int t = 0; t < njobs; t++) {
        const int cur = t & 1, nxt = cur ^ 1;
        const int mtile = slot + t * 148;
        const int r0 = mtile * 128;
        if (tid < 128) { sbest[tid] = ~0ULL; ssec[tid] = ~0ULL; xred[nxt * 128 + tid] = 0.f; }
        __syncthreads();                              // (a) init + A[cur] visible

        const uint32_t abuf = cur * 34816;
        float best[4], sec[4];
        int bc[4];
        #pragma unroll
        for (int rs = 0; rs < 4; rs++) { best[rs] = 3.4e38f; sec[rs] = 3.4e38f; bc[rs] = 0; }

        #pragma unroll
        for (int ng = 0; ng < 2; ng++) {
            const uint32_t boff = ng * (256 * APITCH);
            float acc[2][8][4];
            #pragma unroll
            for (int mt = 0; mt < 2; mt++)
                #pragma unroll
                for (int nt = 0; nt < 8; nt++)
                    #pragma unroll
                    for (int q = 0; q < 4; q++) acc[mt][nt][q] = 0.f;

            #pragma unroll
            for (int ks = 0; ks < 8; ks++) {
                const int kb = ks * 32;
                uint32_t ah[2][4], bb[4][4];
                #pragma unroll
                for (int mt = 0; mt < 2; mt++) ldsm4(ah[mt], a_addr[mt] + abuf + kb);
                #pragma unroll
                for (int p = 0; p < 4; p++) ldsm4(bb[p], b_addr[p] + boff + kb);
                #pragma unroll
                for (int mt = 0; mt < 2; mt++)
                    #pragma unroll
                    for (int p = 0; p < 4; p++) {
                        mma16816(acc[mt][2 * p],     ah[mt], &bb[p][0]);
                        mma16816(acc[mt][2 * p + 1], ah[mt], &bb[p][2]);
                    }
            }
            #pragma unroll
            for (int rs = 0; rs < 4; rs++) {
                const int mt = rs >> 1, rh = rs & 1;
                #pragma unroll
                for (int nt = 0; nt < 8; nt++)
                    #pragma unroll
                    for (int q = 0; q < 2; q++) {
                        int col = ng * 256 + nc + nt * 8 + t4 * 2 + q;
                        float dist = fmaf(-2.f, acc[mt][nt][rh * 2 + q], en_s[col]);
                        if (dist < best[rs]) { sec[rs] = best[rs]; best[rs] = dist; bc[rs] = col; }
                        else if (dist < sec[rs]) sec[rs] = dist;
                    }
            }
            if (ng == 0 && t + 1 < njobs) prefetch(slot + (t + 1) * 148, nxt);
        }

        // best phase, then exact second phase
        unsigned long long bkey[4];
        #pragma unroll
        for (int rs = 0; rs < 4; rs++) {
            bkey[rs] = ((unsigned long long)fenc(best[rs]) << 32) | (unsigned)bc[rs];
            atomicMin(&sbest[mr + (rs >> 1) * 16 + (lane >> 2) + (rs & 1) * 8], bkey[rs]);
        }
        __syncthreads();                              // (b)
        #pragma unroll
        for (int rs = 0; rs < 4; rs++) {
            const int row = mr + (rs >> 1) * 16 + (lane >> 2) + (rs & 1) * 8;
            unsigned long long cand = (bkey[rs] == sbest[row])
                ? (((unsigned long long)fenc(sec[rs]) << 32) | 0x3FFu)
                : bkey[rs];
            atomicMin(&ssec[row], cand);
        }
        __syncthreads();                              // (c)

        // decode: idx outputs, histogram, loss partial, margin flags
        if (tid < 128) {
            unsigned long long gb = sbest[tid];
            g_minkey[r0 + tid] = gb;
            int code = (int)(gb & 0x3FFu);
            s_idx[tid] = code;
            out[OFF_IDX + r0 + tid] = (float)code;
            g_idx[r0 + tid] = code;
            atomicAdd(&g_counts[code], 1);
            lred[tid] = xred[cur * 128 + tid] + fdec((unsigned)(gb >> 32));
            float margin = fdec((unsigned)(ssec[tid] >> 32)) - fdec((unsigned)(gb >> 32));
            if (margin < TAU) {
                int jx = atomicAdd(&g_nfix, 1);
                g_fixlist[jx] = r0 + tid;
            }
        }
        __syncthreads();                              // (d) s_idx + lred ready

        if (tid < 32) {
            float s = lred[tid] + lred[tid + 32] + lred[tid + 64] + lred[tid + 96];
            #pragma unroll
            for (int o = 16; o; o >>= 1) s += __shfl_xor_sync(0xFFFFFFFFu, s, o);
            if (tid == 0) atomicAdd(&g_loss, s);
        }
        // gather: write quantized tile (overlaps into next tile's compute)
        {
            const size_t qb = OFF_Q + (size_t)(mtile >> 5) * ZSTRB + ((mtile & 31) << 7);
            for (int i = tid; i < 16384; i += 512) {
                int d = i >> 7, rr = i & 127;
                out[qb + (size_t)d * HW + rr] = emb[d * KCODES + s_idx[rr]];
            }
        }
    }
}

// ---------------- K: exact re-scan + delta correction ----------------
__global__ __launch_bounds__(512)
void k_fixup(const float* __restrict__ z, const float* __restrict__ emb,
             float* __restrict__ out) {
    __shared__ float zr[FIXB][DIMS];
    __shared__ int rows[FIXB];
    __shared__ int chg[FIXB];
    __shared__ unsigned long long sk[FIXB];
    const int tid = threadIdx.x;                       // 512 (= one code each)
    const int n = g_nfix;
    for (int base = blockIdx.x * FIXB; base < n; base += gridDim.x * FIXB) {
        const int nb = min(FIXB, n - base);
        if (tid < nb) { rows[tid] = g_fixlist[base + tid]; sk[tid] = ~0ULL; }
        __syncthreads();
        for (int i = tid; i < nb * DIMS; i += 512) {
            int j = i >> 7, d = i & 127;
            int row = rows[j];
            zr[j][d] = z[(size_t)(row >> 12) * ZSTRB + (size_t)d * HW + (row & 4095)];
        }
        __syncthreads();
        float dots[FIXB];
        #pragma unroll
        for (int j = 0; j < FIXB; j++) dots[j] = 0.f;
        for (int d = 0; d < DIMS; d++) {
            float e = emb[d * KCODES + tid];            // coalesced, L2-resident
            #pragma unroll
            for (int j = 0; j < FIXB; j++)
                dots[j] = fmaf(zr[j][d], e, dots[j]);
        }
        const float en = g_enorm[tid];
        #pragma unroll
        for (int j = 0; j < FIXB; j++) {
            float dist = fmaf(-2.f, dots[j], en);
            unsigned long long key =
                ((unsigned long long)fenc(dist) << 32) | (unsigned)tid;
            #pragma unroll
            for (int o = 16; o; o >>= 1) {
                unsigned long long other = __shfl_xor_sync(0xFFFFFFFFu, key, o);
                if (other < key) key = other;
            }
            if ((tid & 31) == 0) atomicMin(&sk[j], key);
        }
        __syncthreads();
        // delta correction
        if (tid < nb) {
            const int row = rows[tid];
            unsigned long long oldk = g_minkey[row];
            unsigned long long newk = sk[tid];
            g_minkey[row] = newk;
            int oldc = (int)(oldk & 0x3FFu), newc = (int)(newk & 0x3FFu);
            atomicAdd(&g_loss, fdec((unsigned)(newk >> 32)) - fdec((unsigned)(oldk >> 32)));
            chg[tid] = -1;
            if (oldc != newc) {
                chg[tid] = newc;
                atomicAdd(&g_counts[oldc], -1);
                atomicAdd(&g_counts[newc], 1);
                out[OFF_IDX + row] = (float)newc;
                g_idx[row] = newc;
            }
        }
        __syncthreads();
        // rewrite quantized column for changed rows only
        for (int i = tid; i < nb * DIMS; i += 512) {
            int j = i >> 7, d = i & 127;
            int ncode = chg[j];
            if (ncode >= 0) {
                int row = rows[j];
                out[OFF_Q + (size_t)(row >> 12) * ZSTRB + (size_t)d * HW + (row & 4095)] =
                    emb[d * KCODES + ncode];
            }
        }
        __syncthreads();
    }
}

// ---------------- K: cluster-size EMA + smoothing ----------------
__global__ void k_stats(const float* __restrict__ cs_in, float* __restrict__ out) {
    __shared__ float sh[KCODES];
    int k = threadIdx.x;                               // 512
    float ncs = cs_in[k] * 0.99f + 0.01f * (float)g_counts[k];
    out[OFF_CS + k] = ncs;
    sh[k] = ncs;
    __syncthreads();
    for (int s = 256; s > 0; s >>= 1) {
        if (k < s) sh[k] += sh[k + s];
        __syncthreads();
    }
    float n = fmaxf(sh[0], 1e-5f);
    g_cs[k] = (ncs + 1e-5f) / (n + KCODES * 1e-5f) * n;
}

// ---------------- K: embed_sum (shared privatized bins) ----------------
__global__ void k_esum(const float* __restrict__ z) {
    __shared__ float accs[KCODES];
    const int d = blockIdx.x, c = blockIdx.y;
    const int tid = threadIdx.x;                       // 256
    accs[tid] = 0.f; accs[tid + 256] = 0.f;
    __syncthreads();
    const float* zp = z + (size_t)c * ZSTRB + (size_t)d * HW;
    const int* ip = g_idx + c * HW;
    for (int i = tid; i < HW; i += 256)
        atomicAdd(&accs[ip[i]], zp[i]);
    __syncthreads();
    float v0 = accs[tid], v1 = accs[tid + 256];
    if (v0 != 0.f) atomicAdd(&g_embed_sum[d * KCODES + tid], v0);
    if (v1 != 0.f) atomicAdd(&g_embed_sum[d * KCODES + tid + 256], v1);
}

// ---------------- K: finalize ----------------
__global__ void k_final(const float* __restrict__ ea_in, float* __restrict__ out) {
    int i = blockIdx.x * 256 + threadIdx.x;            // 256 x 256
    float ea = ea_in[i] * 0.99f + 0.01f * g_embed_sum[i];
    out[OFF_EA + i] = ea;
    out[OFF_EMB + i] = ea / g_cs[i & (KCODES - 1)];
    if (i == 0) out[OFF_LOSS] = 1.25f * g_loss * (1.f / 16777216.f);
}

extern "C" void kernel_launch(void* const* d_in, const int* in_sizes, int n_in,
                              void* d_out, int out_size) {
    const float* z   = (const float*)d_in[0];
    const float* emb = (const float*)d_in[1];
    const float* cs  = (const float*)d_in[2];
    const float* ea  = (const float*)d_in[3];
    float* out = (float*)d_out;

    cudaFuncSetAttribute(k_gemm, cudaFuncAttributeMaxDynamicSharedMemorySize, SM_GEMM);

    k_zero<<<256, 256>>>();
    k_bsplit<<<128, 512>>>(emb);
    k_enorm<<<2, 256>>>(emb);
    k_gemm<<<148, 512, SM_GEMM>>>(z, emb, out);
    k_fixup<<<592, 512>>>(z, emb, out);
    k_stats<<<1, 512>>>(cs, out);
    k_esum<<<dim3(128, 32), 256>>>(z);
    k_final<<<256, 256>>>(ea, out);
}

// round 14
// speedup vs baseline: 1.1549x; 1.1549x over previous
#include <cuda_runtime.h>
#include <cuda_fp16.h>
#include <stdint.h>

#define DIMS   128
#define KCODES 512
#define NB     32
#define HW     4096
#define NROWS  131072
#define ZSTRB  524288

#define OFF_Q    ((size_t)0)
#define OFF_LOSS ((size_t)16777216)
#define OFF_IDX  ((size_t)16777217)
#define OFF_EMB  ((size_t)16908289)
#define OFF_CS   ((size_t)16973825)
#define OFF_EA   ((size_t)16974337)

#define TAU 0.12f
#define FIXB 16

// ---------------- device scratch ----------------
__device__ __half g_Bh[KCODES * DIMS];       // emb hi split, [code][d]
__device__ unsigned long long g_minkey[NROWS];
__device__ float g_embed_sum[DIMS * KCODES];
__device__ int   g_counts[KCODES];
__device__ float g_loss;
__device__ float g_enorm[KCODES];
__device__ float g_cs[KCODES];
__device__ int   g_idx[NROWS];
__device__ int   g_nfix;
__device__ int   g_fixlist[NROWS];

// ---------------- helpers ----------------
__device__ __forceinline__ unsigned fenc(float f) {
    unsigned u = __float_as_uint(f);
    return (u & 0x80000000u) ? ~u : (u | 0x80000000u);
}
__device__ __forceinline__ float fdec(unsigned e) {
    return (e & 0x80000000u) ? __uint_as_float(e ^ 0x80000000u)
                             : __uint_as_float(~e);
}
__device__ __forceinline__ void mma16816(float* d, const uint32_t* a, const uint32_t* b) {
    asm volatile(
        "mma.sync.aligned.m16n8k16.row.col.f32.f16.f16.f32 "
        "{%0,%1,%2,%3}, {%4,%5,%6,%7}, {%8,%9}, {%0,%1,%2,%3};"
        : "+f"(d[0]), "+f"(d[1]), "+f"(d[2]), "+f"(d[3])
        : "r"(a[0]), "r"(a[1]), "r"(a[2]), "r"(a[3]), "r"(b[0]), "r"(b[1]));
}
__device__ __forceinline__ void ldsm4(uint32_t* r, uint32_t addr) {
    asm volatile(
        "ldmatrix.sync.aligned.m8n8.x4.shared.b16 {%0,%1,%2,%3}, [%4];"
        : "=r"(r[0]), "=r"(r[1]), "=r"(r[2]), "=r"(r[3]) : "r"(addr));
}

// ---------------- K: zero scratch ----------------
__global__ void k_zero() {
    int i = blockIdx.x * 256 + threadIdx.x;            // 256 x 256
    g_embed_sum[i] = 0.f;
    if (i < KCODES) g_counts[i] = 0;
    if (i == 0) { g_loss = 0.f; g_nfix = 0; }
}

// ---------------- K: embedding hi split + norms ----------------
__global__ void k_bsplit(const float* __restrict__ emb) {
    int d = blockIdx.x;                                // 128
    int k = threadIdx.x;                               // 512
    g_Bh[(size_t)k * DIMS + d] = __float2half_rn(emb[d * KCODES + k]);
}

__global__ void k_enorm(const float* __restrict__ emb) {
    int k = blockIdx.x * 256 + threadIdx.x;            // 2 x 256
    float s = 0.f;
    #pragma unroll 8
    for (int d = 0; d < DIMS; d++) {
        float e = emb[d * KCODES + k];
        s = fmaf(e, e, s);
    }
    g_enorm[k] = s;
}

// ---------------- K: persistent fused GEMM + argmin + decode tail ----------
#define APITCH 272
#define SB_OFF 0                           // 512 x 272 = 139264
#define SA0    139264                      // 2 x 34816 A buffers
#define EN_OFF 208896                      // 512 floats
#define SBEST  210944                      // 128 u64
#define SSEC   211968                      // 128 u64
#define XRED2  212992                      // 2 x 128 floats
#define LRED   214016                      // 128 floats
#define SM_GEMM 214528

__global__ __launch_bounds__(512, 1)
void k_gemm(const float* __restrict__ z, float* __restrict__ out) {
    extern __shared__ char smc[];
    const int tid = threadIdx.x;
    const int wid = tid >> 5, lane = tid & 31;
    const int t4 = lane & 3;
    const int slot = blockIdx.x;                      // 0..147
    const int njobs = (1023 - slot) / 148 + 1;        // 6 or 7 tiles
    const int mr = (wid & 3) * 32;                    // warp row base
    const int nc = (wid >> 2) * 64;                   // warp col base

    float* en_s = (float*)(smc + EN_OFF);
    unsigned long long* sbest = (unsigned long long*)(smc + SBEST);
    unsigned long long* ssec  = (unsigned long long*)(smc + SSEC);
    float* xred = (float*)(smc + XRED2);              // [2][128]
    float* lred = (float*)(smc + LRED);

    // B: all 512 codes resident, loaded ONCE
    for (int i = tid; i < 8192; i += 512) {
        int row = i >> 4, c = i & 15;
        *(uint4*)(smc + SB_OFF + row * APITCH + c * 16) =
            *(const uint4*)(g_Bh + (size_t)row * DIMS + c * 8);
    }
    en_s[tid] = g_enorm[tid];
    if (tid < 128) xred[tid] = 0.f;                   // buffer 0
    __syncthreads();

    const int r = tid & 127, j = tid >> 7;            // j = 0..3
    auto prefetch = [&](int mt, int buf) {
        const float* zp = z + (size_t)(mt >> 5) * ZSTRB + ((mt & 31) << 7) + r;
        float xn = 0.f;
        #pragma unroll
        for (int it = 0; it < 16; it++) {
            const int dp = j + 4 * it;                // dim pair 0..63
            float a = zp[(size_t)(2 * dp) * HW];
            float b = zp[(size_t)(2 * dp + 1) * HW];
            *(__half2*)(smc + SA0 + buf * 34816 + r * APITCH + dp * 4) =
                __floats2half2_rn(a, b);
            xn = fmaf(a, a, fmaf(b, b, xn));
        }
        atomicAdd(&xred[buf * 128 + r], xn);
    };
    prefetch(slot, 0);                                // fill A[0] for tile 0

    const uint32_t sa = (uint32_t)__cvta_generic_to_shared(smc + SA0);
    const uint32_t sb = (uint32_t)__cvta_generic_to_shared(smc + SB_OFF);
    uint32_t a_addr[2], b_addr[4];
    #pragma unroll
    for (int mt = 0; mt < 2; mt++)
        a_addr[mt] = sa + (mr + mt * 16 + (lane & 15)) * APITCH + ((lane >> 4) << 4);
    #pragma unroll
    for (int p = 0; p < 4; p++)
        b_addr[p] = sb + (nc + p * 16 + ((lane >> 4) << 3) + (lane & 7)) * APITCH
                       + (((lane >> 3) & 1) << 4);

    for (int t = 0; t < njobs; t++) {
        const int cur = t & 1, nxt = cur ^ 1;
        const int mtile = slot + t * 148;
        const int r0 = mtile * 128;
        if (tid < 128) { sbest[tid] = ~0ULL; ssec[tid] = ~0ULL; xred[nxt * 128 + tid] = 0.f; }
        __syncthreads();                              // (a) init + A[cur] visible

        const uint32_t abuf = cur * 34816;
        float best[4], sec[4];
        int bc[4];
        #pragma unroll
        for (int rs = 0; rs < 4; rs++) { best[rs] = 3.4e38f; sec[rs] = 3.4e38f; bc[rs] = 0; }

        #pragma unroll
        for (int ng = 0; ng < 2; ng++) {
            const uint32_t boff = ng * (256 * APITCH);
            float acc[2][8][4];
            #pragma unroll
            for (int mt = 0; mt < 2; mt++)
                #pragma unroll
                for (int nt = 0; nt < 8; nt++)
                    #pragma unroll
                    for (int q = 0; q < 4; q++) acc[mt][nt][q] = 0.f;

            #pragma unroll
            for (int ks = 0; ks < 8; ks++) {
                const int kb = ks * 32;
                uint32_t ah[2][4], bb[4][4];
                #pragma unroll
                for (int mt = 0; mt < 2; mt++) ldsm4(ah[mt], a_addr[mt] + abuf + kb);
                #pragma unroll
                for (int p = 0; p < 4; p++) ldsm4(bb[p], b_addr[p] + boff + kb);
                #pragma unroll
                for (int mt = 0; mt < 2; mt++)
                    #pragma unroll
                    for (int p = 0; p < 4; p++) {
                        mma16816(acc[mt][2 * p],     ah[mt], &bb[p][0]);
                        mma16816(acc[mt][2 * p + 1], ah[mt], &bb[p][2]);
                    }
            }
            #pragma unroll
            for (int rs = 0; rs < 4; rs++) {
                const int mt = rs >> 1, rh = rs & 1;
                #pragma unroll
                for (int nt = 0; nt < 8; nt++)
                    #pragma unroll
                    for (int q = 0; q < 2; q++) {
                        int col = ng * 256 + nc + nt * 8 + t4 * 2 + q;
                        float dist = fmaf(-2.f, acc[mt][nt][rh * 2 + q], en_s[col]);
                        if (dist < best[rs]) { sec[rs] = best[rs]; best[rs] = dist; bc[rs] = col; }
                        else if (dist < sec[rs]) sec[rs] = dist;
                    }
            }
            if (ng == 0 && t + 1 < njobs) prefetch(slot + (t + 1) * 148, nxt);
        }

        // best phase, then exact second phase
        unsigned long long bkey[4];
        #pragma unroll
        for (int rs = 0; rs < 4; rs++) {
            bkey[rs] = ((unsigned long long)fenc(best[rs]) << 32) | (unsigned)bc[rs];
            atomicMin(&sbest[mr + (rs >> 1) * 16 + (lane >> 2) + (rs & 1) * 8], bkey[rs]);
        }
        __syncthreads();                              // (b)
        #pragma unroll
        for (int rs = 0; rs < 4; rs++) {
            const int row = mr + (rs >> 1) * 16 + (lane >> 2) + (rs & 1) * 8;
            unsigned long long cand = (bkey[rs] == sbest[row])
                ? (((unsigned long long)fenc(sec[rs]) << 32) | 0x3FFu)
                : bkey[rs];
            atomicMin(&ssec[row], cand);
        }
        __syncthreads();                              // (c)

        // decode tail: idx outputs, histogram, loss partial, margin flags
        if (tid < 128) {
            unsigned long long gb = sbest[tid];
            g_minkey[r0 + tid] = gb;
            int code = (int)(gb & 0x3FFu);
            out[OFF_IDX + r0 + tid] = (float)code;
            g_idx[r0 + tid] = code;
            atomicAdd(&g_counts[code], 1);
            lred[tid] = xred[cur * 128 + tid] + fdec((unsigned)(gb >> 32));
            float margin = fdec((unsigned)(ssec[tid] >> 32)) - fdec((unsigned)(gb >> 32));
            if (margin < TAU) {
                int jx = atomicAdd(&g_nfix, 1);
                g_fixlist[jx] = r0 + tid;
            }
        }
        __syncthreads();                              // (d) lred ready
        if (tid < 32) {
            float s = lred[tid] + lred[tid + 32] + lred[tid + 64] + lred[tid + 96];
            #pragma unroll
            for (int o = 16; o; o >>= 1) s += __shfl_xor_sync(0xFFFFFFFFu, s, o);
            if (tid == 0) atomicAdd(&g_loss, s);
        }
    }
}

// ---------------- K: quantized gather (standalone, latency-hidden) --------
__global__ void k_gather(const float* __restrict__ emb, float* __restrict__ out) {
    __shared__ int idxs[128];
    const int tid = threadIdx.x, blk = blockIdx.x;     // 1024 x 256
    const int b = blk >> 5, s0 = (blk & 31) << 7;
    if (tid < 128) idxs[tid] = g_idx[blk * 128 + tid];
    __syncthreads();
    for (int i = tid; i < 16384; i += 256) {
        int d = i >> 7, r = i & 127;
        out[OFF_Q + (size_t)b * ZSTRB + (size_t)d * HW + s0 + r] = emb[d * KCODES + idxs[r]];
    }
}

// ---------------- K: exact re-scan + delta correction ----------------
__global__ __launch_bounds__(512)
void k_fixup(const float* __restrict__ z, const float* __restrict__ emb,
             float* __restrict__ out) {
    __shared__ float zr[FIXB][DIMS];
    __shared__ int rows[FIXB];
    __shared__ int chg[FIXB];
    __shared__ unsigned long long sk[FIXB];
    const int tid = threadIdx.x;                       // 512 (= one code each)
    const int n = g_nfix;
    for (int base = blockIdx.x * FIXB; base < n; base += gridDim.x * FIXB) {
        const int nb = min(FIXB, n - base);
        if (tid < nb) { rows[tid] = g_fixlist[base + tid]; sk[tid] = ~0ULL; }
        __syncthreads();
        for (int i = tid; i < nb * DIMS; i += 512) {
            int j = i >> 7, d = i & 127;
            int row = rows[j];
            zr[j][d] = z[(size_t)(row >> 12) * ZSTRB + (size_t)d * HW + (row & 4095)];
        }
        __syncthreads();
        float dots[FIXB];
        #pragma unroll
        for (int j = 0; j < FIXB; j++) dots[j] = 0.f;
        for (int d = 0; d < DIMS; d++) {
            float e = emb[d * KCODES + tid];            // coalesced, L2-resident
            #pragma unroll
            for (int j = 0; j < FIXB; j++)
                dots[j] = fmaf(zr[j][d], e, dots[j]);
        }
        const float en = g_enorm[tid];
        #pragma unroll
        for (int j = 0; j < FIXB; j++) {
            float dist = fmaf(-2.f, dots[j], en);
            unsigned long long key =
                ((unsigned long long)fenc(dist) << 32) | (unsigned)tid;
            #pragma unroll
            for (int o = 16; o; o >>= 1) {
                unsigned long long other = __shfl_xor_sync(0xFFFFFFFFu, key, o);
                if (other < key) key = other;
            }
            if ((tid & 31) == 0) atomicMin(&sk[j], key);
        }
        __syncthreads();
        // delta correction
        if (tid < nb) {
            const int row = rows[tid];
            unsigned long long oldk = g_minkey[row];
            unsigned long long newk = sk[tid];
            g_minkey[row] = newk;
            int oldc = (int)(oldk & 0x3FFu), newc = (int)(newk & 0x3FFu);
            atomicAdd(&g_loss, fdec((unsigned)(newk >> 32)) - fdec((unsigned)(oldk >> 32)));
            chg[tid] = -1;
            if (oldc != newc) {
                chg[tid] = newc;
                atomicAdd(&g_counts[oldc], -1);
                atomicAdd(&g_counts[newc], 1);
                out[OFF_IDX + row] = (float)newc;
                g_idx[row] = newc;
            }
        }
        __syncthreads();
        // rewrite quantized column for changed rows only
        for (int i = tid; i < nb * DIMS; i += 512) {
            int j = i >> 7, d = i & 127;
            int ncode = chg[j];
            if (ncode >= 0) {
                int row = rows[j];
                out[OFF_Q + (size_t)(row >> 12) * ZSTRB + (size_t)d * HW + (row & 4095)] =
                    emb[d * KCODES + ncode];
            }
        }
        __syncthreads();
    }
}

// ---------------- K: cluster-size EMA + smoothing ----------------
__global__ void k_stats(const float* __restrict__ cs_in, float* __restrict__ out) {
    __shared__ float sh[KCODES];
    int k = threadIdx.x;                               // 512
    float ncs = cs_in[k] * 0.99f + 0.01f * (float)g_counts[k];
    out[OFF_CS + k] = ncs;
    sh[k] = ncs;
    __syncthreads();
    for (int s = 256; s > 0; s >>= 1) {
        if (k < s) sh[k] += sh[k + s];
        __syncthreads();
    }
    float n = fmaxf(sh[0], 1e-5f);
    g_cs[k] = (ncs + 1e-5f) / (n + KCODES * 1e-5f) * n;
}

// ---------------- K: embed_sum, 4-way bank-spread bins ----------------
__global__ void k_esum(const float* __restrict__ z) {
    __shared__ float accs[KCODES * 4];                 // [code][copy]
    const int d = blockIdx.x, c = blockIdx.y;
    const int tid = threadIdx.x;                       // 256
    #pragma unroll
    for (int i = 0; i < 8; i++) accs[tid + 256 * i] = 0.f;
    __syncthreads();
    const float* zp = z + (size_t)c * ZSTRB + (size_t)d * HW;
    const int* ip = g_idx + c * HW;
    const int cp = tid & 3;
    for (int i = tid; i < HW; i += 256)
        atomicAdd(&accs[ip[i] * 4 + cp], zp[i]);
    __syncthreads();
    float v0 = accs[tid * 4] + accs[tid * 4 + 1] + accs[tid * 4 + 2] + accs[tid * 4 + 3];
    int t2 = tid + 256;
    float v1 = accs[t2 * 4] + accs[t2 * 4 + 1] + accs[t2 * 4 + 2] + accs[t2 * 4 + 3];
    if (v0 != 0.f) atomicAdd(&g_embed_sum[d * KCODES + tid], v0);
    if (v1 != 0.f) atomicAdd(&g_embed_sum[d * KCODES + t2], v1);
}

// ---------------- K: finalize ----------------
__global__ void k_final(const float* __restrict__ ea_in, float* __restrict__ out) {
    int i = blockIdx.x * 256 + threadIdx.x;            // 256 x 256
    float ea = ea_in[i] * 0.99f + 0.01f * g_embed_sum[i];
    out[OFF_EA + i] = ea;
    out[OFF_EMB + i] = ea / g_cs[i & (KCODES - 1)];
    if (i == 0) out[OFF_LOSS] = 1.25f * g_loss * (1.f / 16777216.f);
}

extern "C" void kernel_launch(void* const* d_in, const int* in_sizes, int n_in,
                              void* d_out, int out_size) {
    const float* z   = (const float*)d_in[0];
    const float* emb = (const float*)d_in[1];
    const float* cs  = (const float*)d_in[2];
    const float* ea  = (const float*)d_in[3];
    float* out = (float*)d_out;

    cudaFuncSetAttribute(k_gemm, cudaFuncAttributeMaxDynamicSharedMemorySize, SM_GEMM);

    k_zero<<<256, 256>>>();
    k_bsplit<<<128, 512>>>(emb);
    k_enorm<<<2, 256>>>(emb);
    k_gemm<<<148, 512, SM_GEMM>>>(z, out);
    k_gather<<<1024, 256>>>(emb, out);
    k_fixup<<<592, 512>>>(z, emb, out);
    k_stats<<<1, 512>>>(cs, out);
    k_esum<<<dim3(128, 32), 256>>>(z);
    k_final<<<256, 256>>>(ea, out);
}

// round 15
// speedup vs baseline: 1.2336x; 1.0681x over previous
#include <cuda_runtime.h>
#include <cuda_fp16.h>
#include <stdint.h>

#define DIMS   128
#define KCODES 512
#define NB     32
#define HW     4096
#define NROWS  131072
#define ZSTRB  524288

#define OFF_Q    ((size_t)0)
#define OFF_LOSS ((size_t)16777216)
#define OFF_IDX  ((size_t)16777217)
#define OFF_EMB  ((size_t)16908289)
#define OFF_CS   ((size_t)16973825)
#define OFF_EA   ((size_t)16974337)

#define TAU 0.12f
#define FIXB 16

// ---------------- device scratch ----------------
__device__ __half g_Bh[KCODES * DIMS];       // emb hi split, [code][d]
__device__ unsigned long long g_minkey[NROWS];
__device__ float g_embed_sum[DIMS * KCODES];
__device__ int   g_counts[KCODES];
__device__ float g_loss;
__device__ float g_enorm[KCODES];
__device__ float g_cs[KCODES];
__device__ int   g_idx[NROWS];
__device__ int   g_nfix;
__device__ int   g_fixlist[NROWS];

// ---------------- helpers ----------------
__device__ __forceinline__ unsigned fenc(float f) {
    unsigned u = __float_as_uint(f);
    return (u & 0x80000000u) ? ~u : (u | 0x80000000u);
}
__device__ __forceinline__ float fdec(unsigned e) {
    return (e & 0x80000000u) ? __uint_as_float(e ^ 0x80000000u)
                             : __uint_as_float(~e);
}
__device__ __forceinline__ void mma16816(float* d, const uint32_t* a, const uint32_t* b) {
    asm volatile(
        "mma.sync.aligned.m16n8k16.row.col.f32.f16.f16.f32 "
        "{%0,%1,%2,%3}, {%4,%5,%6,%7}, {%8,%9}, {%0,%1,%2,%3};"
        : "+f"(d[0]), "+f"(d[1]), "+f"(d[2]), "+f"(d[3])
        : "r"(a[0]), "r"(a[1]), "r"(a[2]), "r"(a[3]), "r"(b[0]), "r"(b[1]));
}
__device__ __forceinline__ void ldsm4(uint32_t* r, uint32_t addr) {
    asm volatile(
        "ldmatrix.sync.aligned.m8n8.x4.shared.b16 {%0,%1,%2,%3}, [%4];"
        : "=r"(r[0]), "=r"(r[1]), "=r"(r[2]), "=r"(r[3]) : "r"(addr));
}

// ---------------- K: zero scratch ----------------
__global__ void k_zero() {
    int i = blockIdx.x * 256 + threadIdx.x;            // 256 x 256
    g_embed_sum[i] = 0.f;
    if (i < KCODES) g_counts[i] = 0;
    if (i == 0) { g_loss = 0.f; g_nfix = 0; }
}

// ---------------- K: prep = bsplit + enorm via smem transpose ----------------
__global__ void k_prep(const float* __restrict__ emb) {
    __shared__ float sm[128 * 129];                    // 66KB static is too big; use dynamic
    const int tid = threadIdx.x;                       // 256
    const int k0 = blockIdx.x * 128;                   // 4 blocks
    for (int i = tid; i < 16384; i += 256) {
        int d = i >> 7, kk = i & 127;
        sm[d * 129 + kk] = emb[d * KCODES + k0 + kk];  // coalesced over kk
    }
    __syncthreads();
    for (int i = tid; i < 16384; i += 256) {
        int kk = i >> 7, d = i & 127;
        g_Bh[(size_t)(k0 + kk) * DIMS + d] = __float2half_rn(sm[d * 129 + kk]);
    }
    if (tid < 128) {
        float s = 0.f;
        #pragma unroll 8
        for (int d = 0; d < DIMS; d++) {
            float v = sm[d * 129 + tid];
            s = fmaf(v, v, s);
        }
        g_enorm[k0 + tid] = s;
    }
}

// ---------------- K: persistent fused GEMM + argmin + decode tail ----------
#define APITCH 272
#define SB_OFF 0                           // 512 x 272 = 139264
#define SA0    139264                      // 2 x 34816 A buffers
#define EN_OFF 208896                      // 512 floats
#define SBEST  210944                      // 128 u64
#define SSEC   211968                      // 128 u64
#define XRED2  212992                      // 2 x 128 floats
#define LRED   214016                      // 128 floats
#define SM_GEMM 214528

__global__ __launch_bounds__(512, 1)
void k_gemm(const float* __restrict__ z, float* __restrict__ out) {
    extern __shared__ char smc[];
    const int tid = threadIdx.x;
    const int wid = tid >> 5, lane = tid & 31;
    const int t4 = lane & 3;
    const int slot = blockIdx.x;                      // 0..147
    const int njobs = (1023 - slot) / 148 + 1;        // 6 or 7 tiles
    const int mr = (wid & 3) * 32;                    // warp row base
    const int nc = (wid >> 2) * 64;                   // warp col base

    float* en_s = (float*)(smc + EN_OFF);
    unsigned long long* sbest = (unsigned long long*)(smc + SBEST);
    unsigned long long* ssec  = (unsigned long long*)(smc + SSEC);
    float* xred = (float*)(smc + XRED2);              // [2][128]
    float* lred = (float*)(smc + LRED);

    // B: all 512 codes resident, loaded ONCE
    for (int i = tid; i < 8192; i += 512) {
        int row = i >> 4, c = i & 15;
        *(uint4*)(smc + SB_OFF + row * APITCH + c * 16) =
            *(const uint4*)(g_Bh + (size_t)row * DIMS + c * 8);
    }
    en_s[tid] = g_enorm[tid];
    if (tid < 128) xred[tid] = 0.f;                   // buffer 0
    __syncthreads();

    const int r = tid & 127, j = tid >> 7;            // j = 0..3
    auto prefetch = [&](int mt, int buf) {
        const float* zp = z + (size_t)(mt >> 5) * ZSTRB + ((mt & 31) << 7) + r;
        float xn = 0.f;
        #pragma unroll
        for (int it = 0; it < 16; it++) {
            const int dp = j + 4 * it;                // dim pair 0..63
            float a = zp[(size_t)(2 * dp) * HW];
            float b = zp[(size_t)(2 * dp + 1) * HW];
            *(__half2*)(smc + SA0 + buf * 34816 + r * APITCH + dp * 4) =
                __floats2half2_rn(a, b);
            xn = fmaf(a, a, fmaf(b, b, xn));
        }
        atomicAdd(&xred[buf * 128 + r], xn);
    };
    prefetch(slot, 0);                                // fill A[0] for tile 0

    const uint32_t sa = (uint32_t)__cvta_generic_to_shared(smc + SA0);
    const uint32_t sb = (uint32_t)__cvta_generic_to_shared(smc + SB_OFF);
    uint32_t a_addr[2], b_addr[4];
    #pragma unroll
    for (int mt = 0; mt < 2; mt++)
        a_addr[mt] = sa + (mr + mt * 16 + (lane & 15)) * APITCH + ((lane >> 4) << 4);
    #pragma unroll
    for (int p = 0; p < 4; p++)
        b_addr[p] = sb + (nc + p * 16 + ((lane >> 4) << 3) + (lane & 7)) * APITCH
                       + (((lane >> 3) & 1) << 4);

    for (int t = 0; t < njobs; t++) {
        const int cur = t & 1, nxt = cur ^ 1;
        const int mtile = slot + t * 148;
        const int r0 = mtile * 128;
        if (tid < 128) { sbest[tid] = ~0ULL; ssec[tid] = ~0ULL; xred[nxt * 128 + tid] = 0.f; }
        __syncthreads();                              // (a) init + A[cur] visible

        const uint32_t abuf = cur * 34816;
        float best[4], sec[4];
        int bc[4];
        #pragma unroll
        for (int rs = 0; rs < 4; rs++) { best[rs] = 3.4e38f; sec[rs] = 3.4e38f; bc[rs] = 0; }

        #pragma unroll
        for (int ng = 0; ng < 2; ng++) {
            const uint32_t boff = ng * (256 * APITCH);
            float acc[2][8][4];
            #pragma unroll
            for (int mt = 0; mt < 2; mt++)
                #pragma unroll
                for (int nt = 0; nt < 8; nt++)
                    #pragma unroll
                    for (int q = 0; q < 4; q++) acc[mt][nt][q] = 0.f;

            #pragma unroll
            for (int ks = 0; ks < 8; ks++) {
                const int kb = ks * 32;
                uint32_t ah[2][4], bb[4][4];
                #pragma unroll
                for (int mt = 0; mt < 2; mt++) ldsm4(ah[mt], a_addr[mt] + abuf + kb);
                #pragma unroll
                for (int p = 0; p < 4; p++) ldsm4(bb[p], b_addr[p] + boff + kb);
                #pragma unroll
                for (int mt = 0; mt < 2; mt++)
                    #pragma unroll
                    for (int p = 0; p < 4; p++) {
                        mma16816(acc[mt][2 * p],     ah[mt], &bb[p][0]);
                        mma16816(acc[mt][2 * p + 1], ah[mt], &bb[p][2]);
                    }
            }
            #pragma unroll
            for (int rs = 0; rs < 4; rs++) {
                const int mt = rs >> 1, rh = rs & 1;
                #pragma unroll
                for (int nt = 0; nt < 8; nt++)
                    #pragma unroll
                    for (int q = 0; q < 2; q++) {
                        int col = ng * 256 + nc + nt * 8 + t4 * 2 + q;
                        float dist = fmaf(-2.f, acc[mt][nt][rh * 2 + q], en_s[col]);
                        if (dist < best[rs]) { sec[rs] = best[rs]; best[rs] = dist; bc[rs] = col; }
                        else if (dist < sec[rs]) sec[rs] = dist;
                    }
            }
            if (ng == 0 && t + 1 < njobs) prefetch(slot + (t + 1) * 148, nxt);
        }

        // best phase, then exact second phase
        unsigned long long bkey[4];
        #pragma unroll
        for (int rs = 0; rs < 4; rs++) {
            bkey[rs] = ((unsigned long long)fenc(best[rs]) << 32) | (unsigned)bc[rs];
            atomicMin(&sbest[mr + (rs >> 1) * 16 + (lane >> 2) + (rs & 1) * 8], bkey[rs]);
        }
        __syncthreads();                              // (b)
        #pragma unroll
        for (int rs = 0; rs < 4; rs++) {
            const int row = mr + (rs >> 1) * 16 + (lane >> 2) + (rs & 1) * 8;
            unsigned long long cand = (bkey[rs] == sbest[row])
                ? (((unsigned long long)fenc(sec[rs]) << 32) | 0x3FFu)
                : bkey[rs];
            atomicMin(&ssec[row], cand);
        }
        __syncthreads();                              // (c)

        // decode tail: idx outputs, histogram, loss partial, margin flags
        if (tid < 128) {
            unsigned long long gb = sbest[tid];
            g_minkey[r0 + tid] = gb;
            int code = (int)(gb & 0x3FFu);
            out[OFF_IDX + r0 + tid] = (float)code;
            g_idx[r0 + tid] = code;
            atomicAdd(&g_counts[code], 1);
            lred[tid] = xred[cur * 128 + tid] + fdec((unsigned)(gb >> 32));
            float margin = fdec((unsigned)(ssec[tid] >> 32)) - fdec((unsigned)(gb >> 32));
            if (margin < TAU) {
                int jx = atomicAdd(&g_nfix, 1);
                g_fixlist[jx] = r0 + tid;
            }
        }
        __syncthreads();                              // (d) lred ready
        if (tid < 32) {
            float s = lred[tid] + lred[tid + 32] + lred[tid + 64] + lred[tid + 96];
            #pragma unroll
            for (int o = 16; o; o >>= 1) s += __shfl_xor_sync(0xFFFFFFFFu, s, o);
            if (tid == 0) atomicAdd(&g_loss, s);
        }
    }
}

// ---------------- K: exact re-scan + delta correction (no quantized patch) --
__global__ __launch_bounds__(512)
void k_fixup(const float* __restrict__ z, const float* __restrict__ emb,
             float* __restrict__ out) {
    __shared__ float zr[FIXB][DIMS];
    __shared__ int rows[FIXB];
    __shared__ unsigned long long sk[FIXB];
    const int tid = threadIdx.x;                       // 512 (= one code each)
    const int n = g_nfix;
    for (int base = blockIdx.x * FIXB; base < n; base += gridDim.x * FIXB) {
        const int nb = min(FIXB, n - base);
        if (tid < nb) { rows[tid] = g_fixlist[base + tid]; sk[tid] = ~0ULL; }
        __syncthreads();
        for (int i = tid; i < nb * DIMS; i += 512) {
            int j = i >> 7, d = i & 127;
            int row = rows[j];
            zr[j][d] = z[(size_t)(row >> 12) * ZSTRB + (size_t)d * HW + (row & 4095)];
        }
        __syncthreads();
        float dots[FIXB];
        #pragma unroll
        for (int j = 0; j < FIXB; j++) dots[j] = 0.f;
        for (int d = 0; d < DIMS; d++) {
            float e = emb[d * KCODES + tid];            // coalesced, L2-resident
            #pragma unroll
            for (int j = 0; j < FIXB; j++)
                dots[j] = fmaf(zr[j][d], e, dots[j]);
        }
        const float en = g_enorm[tid];
        #pragma unroll
        for (int j = 0; j < FIXB; j++) {
            float dist = fmaf(-2.f, dots[j], en);
            unsigned long long key =
                ((unsigned long long)fenc(dist) << 32) | (unsigned)tid;
            #pragma unroll
            for (int o = 16; o; o >>= 1) {
                unsigned long long other = __shfl_xor_sync(0xFFFFFFFFu, key, o);
                if (other < key) key = other;
            }
            if ((tid & 31) == 0) atomicMin(&sk[j], key);
        }
        __syncthreads();
        // delta correction: loss, counts, idx (quantized written later by esumgather)
        if (tid < nb) {
            const int row = rows[tid];
            unsigned long long oldk = g_minkey[row];
            unsigned long long newk = sk[tid];
            int oldc = (int)(oldk & 0x3FFu), newc = (int)(newk & 0x3FFu);
            atomicAdd(&g_loss, fdec((unsigned)(newk >> 32)) - fdec((unsigned)(oldk >> 32)));
            if (oldc != newc) {
                atomicAdd(&g_counts[oldc], -1);
                atomicAdd(&g_counts[newc], 1);
                out[OFF_IDX + row] = (float)newc;
                g_idx[row] = newc;
            }
        }
        __syncthreads();
    }
}

// ---------------- K: embed_sum (4-way spread bins) + quantized gather ------
__global__ void k_esumgather(const float* __restrict__ z,
                             const float* __restrict__ emb,
                             float* __restrict__ out) {
    __shared__ float accs[KCODES * 4];                 // [code][copy]
    __shared__ float erow[KCODES];                     // emb[d][*]
    const int d = blockIdx.x, c = blockIdx.y;
    const int tid = threadIdx.x;                       // 256
    #pragma unroll
    for (int i = 0; i < 8; i++) accs[tid + 256 * i] = 0.f;
    erow[tid] = emb[d * KCODES + tid];
    erow[tid + 256] = emb[d * KCODES + tid + 256];
    __syncthreads();
    const float* zp = z + (size_t)c * ZSTRB + (size_t)d * HW;
    const int* ip = g_idx + c * HW;
    float* op = out + OFF_Q + (size_t)c * ZSTRB + (size_t)d * HW;
    const int cp = tid & 3;
    for (int i = tid; i < HW; i += 256) {
        int code = ip[i];
        atomicAdd(&accs[code * 4 + cp], zp[i]);
        op[i] = erow[code];
    }
    __syncthreads();
    float v0 = accs[tid * 4] + accs[tid * 4 + 1] + accs[tid * 4 + 2] + accs[tid * 4 + 3];
    int t2 = tid + 256;
    float v1 = accs[t2 * 4] + accs[t2 * 4 + 1] + accs[t2 * 4 + 2] + accs[t2 * 4 + 3];
    if (v0 != 0.f) atomicAdd(&g_embed_sum[d * KCODES + tid], v0);
    if (v1 != 0.f) atomicAdd(&g_embed_sum[d * KCODES + t2], v1);
}

// ---------------- K: cluster-size EMA + smoothing ----------------
__global__ void k_stats(const float* __restrict__ cs_in, float* __restrict__ out) {
    __shared__ float sh[KCODES];
    int k = threadIdx.x;                               // 512
    float ncs = cs_in[k] * 0.99f + 0.01f * (float)g_counts[k];
    out[OFF_CS + k] = ncs;
    sh[k] = ncs;
    __syncthreads();
    for (int s = 256; s > 0; s >>= 1) {
        if (k < s) sh[k] += sh[k + s];
        __syncthreads();
    }
    float n = fmaxf(sh[0], 1e-5f);
    g_cs[k] = (ncs + 1e-5f) / (n + KCODES * 1e-5f) * n;
}

// ---------------- K: finalize ----------------
__global__ void k_final(const float* __restrict__ ea_in, float* __restrict__ out) {
    int i = blockIdx.x * 256 + threadIdx.x;            // 256 x 256
    float ea = ea_in[i] * 0.99f + 0.01f * g_embed_sum[i];
    out[OFF_EA + i] = ea;
    out[OFF_EMB + i] = ea / g_cs[i & (KCODES - 1)];
    if (i == 0) out[OFF_LOSS] = 1.25f * g_loss * (1.f / 16777216.f);
}

extern "C" void kernel_launch(void* const* d_in, const int* in_sizes, int n_in,
                              void* d_out, int out_size) {
    const float* z   = (const float*)d_in[0];
    const float* emb = (const float*)d_in[1];
    const float* cs  = (const float*)d_in[2];
    const float* ea  = (const float*)d_in[3];
    float* out = (float*)d_out;

    cudaFuncSetAttribute(k_gemm, cudaFuncAttributeMaxDynamicSharedMemorySize, SM_GEMM);

    k_zero<<<256, 256>>>();
    k_prep<<<4, 256>>>(emb);
    k_gemm<<<148, 512, SM_GEMM>>>(z, out);
    k_fixup<<<592, 512>>>(z, emb, out);
    k_esumgather<<<dim3(128, 32), 256>>>(z, emb, out);
    k_stats<<<1, 512>>>(cs, out);
    k_final<<<256, 256>>>(ea, out);
}

// round 16
// speedup vs baseline: 1.2772x; 1.0353x over previous
#include <cuda_runtime.h>
#include <cuda_fp16.h>
#include <stdint.h>

#define DIMS   128
#define KCODES 512
#define NB     32
#define HW     4096
#define NROWS  131072
#define ZSTRB  524288

#define OFF_Q    ((size_t)0)
#define OFF_LOSS ((size_t)16777216)
#define OFF_IDX  ((size_t)16777217)
#define OFF_EMB  ((size_t)16908289)
#define OFF_CS   ((size_t)16973825)
#define OFF_EA   ((size_t)16974337)

#define TAU 0.04f
#define FIXB 16

// ---------------- device scratch ----------------
__device__ __half g_Bh[KCODES * DIMS];       // emb hi split, [code][d]
__device__ unsigned long long g_minkey[NROWS];
__device__ float g_embed_sum[DIMS * KCODES];
__device__ int   g_counts[KCODES];
__device__ float g_loss;
__device__ float g_enorm[KCODES];
__device__ float g_cs[KCODES];
__device__ int   g_idx[NROWS];
__device__ int   g_nfix;
__device__ int   g_fixlist[NROWS];

// ---------------- helpers ----------------
__device__ __forceinline__ unsigned fenc(float f) {
    unsigned u = __float_as_uint(f);
    return (u & 0x80000000u) ? ~u : (u | 0x80000000u);
}
__device__ __forceinline__ float fdec(unsigned e) {
    return (e & 0x80000000u) ? __uint_as_float(e ^ 0x80000000u)
                             : __uint_as_float(~e);
}
__device__ __forceinline__ void mma16816(float* d, const uint32_t* a, const uint32_t* b) {
    asm volatile(
        "mma.sync.aligned.m16n8k16.row.col.f32.f16.f16.f32 "
        "{%0,%1,%2,%3}, {%4,%5,%6,%7}, {%8,%9}, {%0,%1,%2,%3};"
        : "+f"(d[0]), "+f"(d[1]), "+f"(d[2]), "+f"(d[3])
        : "r"(a[0]), "r"(a[1]), "r"(a[2]), "r"(a[3]), "r"(b[0]), "r"(b[1]));
}
__device__ __forceinline__ void ldsm4(uint32_t* r, uint32_t addr) {
    asm volatile(
        "ldmatrix.sync.aligned.m8n8.x4.shared.b16 {%0,%1,%2,%3}, [%4];"
        : "=r"(r[0]), "=r"(r[1]), "=r"(r[2]), "=r"(r[3]) : "r"(addr));
}

// ---------------- K: zero scratch ----------------
__global__ void k_zero() {
    int i = blockIdx.x * 256 + threadIdx.x;            // 256 x 256
    g_embed_sum[i] = 0.f;
    if (i < KCODES) g_counts[i] = 0;
    if (i == 0) { g_loss = 0.f; g_nfix = 0; }
}

// ---------------- K: prep = bsplit + enorm via smem transpose ----------------
__global__ void k_prep(const float* __restrict__ emb) {
    __shared__ float sm[128 * 129];
    const int tid = threadIdx.x;                       // 256
    const int k0 = blockIdx.x * 128;                   // 4 blocks
    for (int i = tid; i < 16384; i += 256) {
        int d = i >> 7, kk = i & 127;
        sm[d * 129 + kk] = emb[d * KCODES + k0 + kk];  // coalesced over kk
    }
    __syncthreads();
    for (int i = tid; i < 16384; i += 256) {
        int kk = i >> 7, d = i & 127;
        g_Bh[(size_t)(k0 + kk) * DIMS + d] = __float2half_rn(sm[d * 129 + kk]);
    }
    if (tid < 128) {
        float s = 0.f;
        #pragma unroll 8
        for (int d = 0; d < DIMS; d++) {
            float v = sm[d * 129 + tid];
            s = fmaf(v, v, s);
        }
        g_enorm[k0 + tid] = s;
    }
}

// ---------------- K: persistent fused GEMM + argmin + decode tail ----------
#define APITCH 272
#define SB_OFF 0                           // 512 x 272 = 139264
#define SA0    139264                      // 2 x 34816 A buffers
#define EN_OFF 208896                      // 512 floats
#define SBEST  210944                      // 128 u64
#define SSEC   211968                      // 128 u64
#define XRED2  212992                      // 2 x 128 floats
#define LRED   214016                      // 128 floats
#define SM_GEMM 214528

__global__ __launch_bounds__(512, 1)
void k_gemm(const float* __restrict__ z, float* __restrict__ out) {
    extern __shared__ char smc[];
    const int tid = threadIdx.x;
    const int wid = tid >> 5, lane = tid & 31;
    const int t4 = lane & 3;
    const int slot = blockIdx.x;                      // 0..147
    const int njobs = (1023 - slot) / 148 + 1;        // 6 or 7 tiles
    const int mr = (wid & 3) * 32;                    // warp row base
    const int nc = (wid >> 2) * 64;                   // warp col base

    float* en_s = (float*)(smc + EN_OFF);
    unsigned long long* sbest = (unsigned long long*)(smc + SBEST);
    unsigned long long* ssec  = (unsigned long long*)(smc + SSEC);
    float* xred = (float*)(smc + XRED2);              // [2][128]
    float* lred = (float*)(smc + LRED);

    // B: all 512 codes resident, loaded ONCE
    for (int i = tid; i < 8192; i += 512) {
        int row = i >> 4, c = i & 15;
        *(uint4*)(smc + SB_OFF + row * APITCH + c * 16) =
            *(const uint4*)(g_Bh + (size_t)row * DIMS + c * 8);
    }
    en_s[tid] = g_enorm[tid];
    if (tid < 128) xred[tid] = 0.f;                   // buffer 0
    __syncthreads();

    const int r = tid & 127, j = tid >> 7;            // j = 0..3
    auto prefetch = [&](int mt, int buf) {
        const float* zp = z + (size_t)(mt >> 5) * ZSTRB + ((mt & 31) << 7) + r;
        float xn = 0.f;
        #pragma unroll
        for (int it = 0; it < 16; it++) {
            const int dp = j + 4 * it;                // dim pair 0..63
            float a = zp[(size_t)(2 * dp) * HW];
            float b = zp[(size_t)(2 * dp + 1) * HW];
            *(__half2*)(smc + SA0 + buf * 34816 + r * APITCH + dp * 4) =
                __floats2half2_rn(a, b);
            xn = fmaf(a, a, fmaf(b, b, xn));
        }
        atomicAdd(&xred[buf * 128 + r], xn);
    };
    prefetch(slot, 0);                                // fill A[0] for tile 0

    const uint32_t sa = (uint32_t)__cvta_generic_to_shared(smc + SA0);
    const uint32_t sb = (uint32_t)__cvta_generic_to_shared(smc + SB_OFF);
    uint32_t a_addr[2], b_addr[4];
    #pragma unroll
    for (int mt = 0; mt < 2; mt++)
        a_addr[mt] = sa + (mr + mt * 16 + (lane & 15)) * APITCH + ((lane >> 4) << 4);
    #pragma unroll
    for (int p = 0; p < 4; p++)
        b_addr[p] = sb + (nc + p * 16 + ((lane >> 4) << 3) + (lane & 7)) * APITCH
                       + (((lane >> 3) & 1) << 4);

    for (int t = 0; t < njobs; t++) {
        const int cur = t & 1, nxt = cur ^ 1;
        const int mtile = slot + t * 148;
        const int r0 = mtile * 128;
        if (tid < 128) { sbest[tid] = ~0ULL; ssec[tid] = ~0ULL; xred[nxt * 128 + tid] = 0.f; }
        __syncthreads();                              // (a) init + A[cur] visible

        const uint32_t abuf = cur * 34816;
        float best[4], sec[4];
        int bc[4];
        #pragma unroll
        for (int rs = 0; rs < 4; rs++) { best[rs] = 3.4e38f; sec[rs] = 3.4e38f; bc[rs] = 0; }

        #pragma unroll
        for (int ng = 0; ng < 2; ng++) {
            const uint32_t boff = ng * (256 * APITCH);
            float acc[2][8][4];
            #pragma unroll
            for (int mt = 0; mt < 2; mt++)
                #pragma unroll
                for (int nt = 0; nt < 8; nt++)
                    #pragma unroll
                    for (int q = 0; q < 4; q++) acc[mt][nt][q] = 0.f;

            #pragma unroll
            for (int ks = 0; ks < 8; ks++) {
                const int kb = ks * 32;
                uint32_t ah[2][4], bb[4][4];
                #pragma unroll
                for (int mt = 0; mt < 2; mt++) ldsm4(ah[mt], a_addr[mt] + abuf + kb);
                #pragma unroll
                for (int p = 0; p < 4; p++) ldsm4(bb[p], b_addr[p] + boff + kb);
                #pragma unroll
                for (int mt = 0; mt < 2; mt++)
                    #pragma unroll
                    for (int p = 0; p < 4; p++) {
                        mma16816(acc[mt][2 * p],     ah[mt], &bb[p][0]);
                        mma16816(acc[mt][2 * p + 1], ah[mt], &bb[p][2]);
                    }
            }
            #pragma unroll
            for (int rs = 0; rs < 4; rs++) {
                const int mt = rs >> 1, rh = rs & 1;
                #pragma unroll
                for (int nt = 0; nt < 8; nt++)
                    #pragma unroll
                    for (int q = 0; q < 2; q++) {
                        int col = ng * 256 + nc + nt * 8 + t4 * 2 + q;
                        float dist = fmaf(-2.f, acc[mt][nt][rh * 2 + q], en_s[col]);
                        if (dist < best[rs]) { sec[rs] = best[rs]; best[rs] = dist; bc[rs] = col; }
                        else if (dist < sec[rs]) sec[rs] = dist;
                    }
            }
            if (ng == 0 && t + 1 < njobs) prefetch(slot + (t + 1) * 148, nxt);
        }

        // best phase, then exact second phase
        unsigned long long bkey[4];
        #pragma unroll
        for (int rs = 0; rs < 4; rs++) {
            bkey[rs] = ((unsigned long long)fenc(best[rs]) << 32) | (unsigned)bc[rs];
            atomicMin(&sbest[mr + (rs >> 1) * 16 + (lane >> 2) + (rs & 1) * 8], bkey[rs]);
        }
        __syncthreads();                              // (b)
        #pragma unroll
        for (int rs = 0; rs < 4; rs++) {
            const int row = mr + (rs >> 1) * 16 + (lane >> 2) + (rs & 1) * 8;
            unsigned long long cand = (bkey[rs] == sbest[row])
                ? (((unsigned long long)fenc(sec[rs]) << 32) | 0x3FFu)
                : bkey[rs];
            atomicMin(&ssec[row], cand);
        }
        __syncthreads();                              // (c)

        // decode tail: idx outputs, histogram, loss partial, margin flags
        if (tid < 128) {
            unsigned long long gb = sbest[tid];
            g_minkey[r0 + tid] = gb;
            int code = (int)(gb & 0x3FFu);
            out[OFF_IDX + r0 + tid] = (float)code;
            g_idx[r0 + tid] = code;
            atomicAdd(&g_counts[code], 1);
            lred[tid] = xred[cur * 128 + tid] + fdec((unsigned)(gb >> 32));
            float margin = fdec((unsigned)(ssec[tid] >> 32)) - fdec((unsigned)(gb >> 32));
            if (margin < TAU) {
                int jx = atomicAdd(&g_nfix, 1);
                g_fixlist[jx] = r0 + tid;
            }
        }
        __syncthreads();                              // (d) lred ready
        if (tid < 32) {
            float s = lred[tid] + lred[tid + 32] + lred[tid + 64] + lred[tid + 96];
            #pragma unroll
            for (int o = 16; o; o >>= 1) s += __shfl_xor_sync(0xFFFFFFFFu, s, o);
            if (tid == 0) atomicAdd(&g_loss, s);
        }
    }
}

// ---------------- K: exact re-scan + delta correction ----------------
__global__ __launch_bounds__(512)
void k_fixup(const float* __restrict__ z, const float* __restrict__ emb,
             float* __restrict__ out) {
    __shared__ float zr[FIXB][DIMS];
    __shared__ int rows[FIXB];
    __shared__ unsigned long long sk[FIXB];
    const int tid = threadIdx.x;                       // 512 (= one code each)
    const int n = g_nfix;
    for (int base = blockIdx.x * FIXB; base < n; base += gridDim.x * FIXB) {
        const int nb = min(FIXB, n - base);
        if (tid < nb) { rows[tid] = g_fixlist[base + tid]; sk[tid] = ~0ULL; }
        __syncthreads();
        for (int i = tid; i < nb * DIMS; i += 512) {
            int j = i >> 7, d = i & 127;
            int row = rows[j];
            zr[j][d] = z[(size_t)(row >> 12) * ZSTRB + (size_t)d * HW + (row & 4095)];
        }
        __syncthreads();
        float dots[FIXB];
        #pragma unroll
        for (int j = 0; j < FIXB; j++) dots[j] = 0.f;
        #pragma unroll 4
        for (int d0 = 0; d0 < DIMS; d0 += 4) {
            float e0 = emb[(d0 + 0) * KCODES + tid];   // coalesced, L2-resident
            float e1 = emb[(d0 + 1) * KCODES + tid];
            float e2 = emb[(d0 + 2) * KCODES + tid];
            float e3 = emb[(d0 + 3) * KCODES + tid];
            #pragma unroll
            for (int j = 0; j < FIXB; j++) {
                float4 zv = *(const float4*)&zr[j][d0];
                dots[j] = fmaf(zv.x, e0,
                          fmaf(zv.y, e1,
                          fmaf(zv.z, e2,
                          fmaf(zv.w, e3, dots[j]))));
            }
        }
        const float en = g_enorm[tid];
        #pragma unroll
        for (int j = 0; j < FIXB; j++) {
            float dist = fmaf(-2.f, dots[j], en);
            unsigned long long key =
                ((unsigned long long)fenc(dist) << 32) | (unsigned)tid;
            #pragma unroll
            for (int o = 16; o; o >>= 1) {
                unsigned long long other = __shfl_xor_sync(0xFFFFFFFFu, key, o);
                if (other < key) key = other;
            }
            if ((tid & 31) == 0) atomicMin(&sk[j], key);
        }
        __syncthreads();
        // delta correction: loss, counts, idx (quantized written by esumgather)
        if (tid < nb) {
            const int row = rows[tid];
            unsigned long long oldk = g_minkey[row];
            unsigned long long newk = sk[tid];
            int oldc = (int)(oldk & 0x3FFu), newc = (int)(newk & 0x3FFu);
            atomicAdd(&g_loss, fdec((unsigned)(newk >> 32)) - fdec((unsigned)(oldk >> 32)));
            if (oldc != newc) {
                atomicAdd(&g_counts[oldc], -1);
                atomicAdd(&g_counts[newc], 1);
                out[OFF_IDX + row] = (float)newc;
                g_idx[row] = newc;
            }
        }
        __syncthreads();
    }
}

// ---------------- K: embed_sum (4-way spread bins) + quantized gather ------
__global__ void k_esumgather(const float* __restrict__ z,
                             const float* __restrict__ emb,
                             float* __restrict__ out) {
    __shared__ float accs[KCODES * 4];                 // [code][copy]
    __shared__ float erow[KCODES];                     // emb[d][*]
    const int d = blockIdx.x, c = blockIdx.y;
    const int tid = threadIdx.x;                       // 256
    #pragma unroll
    for (int i = 0; i < 8; i++) accs[tid + 256 * i] = 0.f;
    erow[tid] = emb[d * KCODES + tid];
    erow[tid + 256] = emb[d * KCODES + tid + 256];
    __syncthreads();
    const float* zp = z + (size_t)c * ZSTRB + (size_t)d * HW;
    const int* ip = g_idx + c * HW;
    float* op = out + OFF_Q + (size_t)c * ZSTRB + (size_t)d * HW;
    const int cp = tid & 3;
    for (int i = tid; i < HW; i += 256) {
        int code = ip[i];
        atomicAdd(&accs[code * 4 + cp], zp[i]);
        op[i] = erow[code];
    }
    __syncthreads();
    float v0 = accs[tid * 4] + accs[tid * 4 + 1] + accs[tid * 4 + 2] + accs[tid * 4 + 3];
    int t2 = tid + 256;
    float v1 = accs[t2 * 4] + accs[t2 * 4 + 1] + accs[t2 * 4 + 2] + accs[t2 * 4 + 3];
    if (v0 != 0.f) atomicAdd(&g_embed_sum[d * KCODES + tid], v0);
    if (v1 != 0.f) atomicAdd(&g_embed_sum[d * KCODES + t2], v1);
}

// ---------------- K: cluster-size EMA + smoothing ----------------
__global__ void k_stats(const float* __restrict__ cs_in, float* __restrict__ out) {
    __shared__ float sh[KCODES];
    int k = threadIdx.x;                               // 512
    float ncs = cs_in[k] * 0.99f + 0.01f * (float)g_counts[k];
    out[OFF_CS + k] = ncs;
    sh[k] = ncs;
    __syncthreads();
    for (int s = 256; s > 0; s >>= 1) {
        if (k < s) sh[k] += sh[k + s];
        __syncthreads();
    }
    float n = fmaxf(sh[0], 1e-5f);
    g_cs[k] = (ncs + 1e-5f) / (n + KCODES * 1e-5f) * n;
}

// ---------------- K: finalize ----------------
__global__ void k_final(const float* __restrict__ ea_in, float* __restrict__ out) {
    int i = blockIdx.x * 256 + threadIdx.x;            // 256 x 256
    float ea = ea_in[i] * 0.99f + 0.01f * g_embed_sum[i];
    out[OFF_EA + i] = ea;
    out[OFF_EMB + i] = ea / g_cs[i & (KCODES - 1)];
    if (i == 0) out[OFF_LOSS] = 1.25f * g_loss * (1.f / 16777216.f);
}

extern "C" void kernel_launch(void* const* d_in, const int* in_sizes, int n_in,
                              void* d_out, int out_size) {
    const float* z   = (const float*)d_in[0];
    const float* emb = (const float*)d_in[1];
    const float* cs  = (const float*)d_in[2];
    const float* ea  = (const float*)d_in[3];
    float* out = (float*)d_out;

    cudaFuncSetAttribute(k_gemm, cudaFuncAttributeMaxDynamicSharedMemorySize, SM_GEMM);

    k_zero<<<256, 256>>>();
    k_prep<<<4, 256>>>(emb);
    k_gemm<<<148, 512, SM_GEMM>>>(z, out);
    k_fixup<<<592, 512>>>(z, emb, out);
    k_esumgather<<<dim3(128, 32), 256>>>(z, emb, out);
    k_stats<<<1, 512>>>(cs, out);
    k_final<<<256, 256>>>(ea, out);
}